// round 1
// baseline (speedup 1.0000x reference)
#include <cuda_runtime.h>
#include <math.h>

#define BB 2
#define SS 2048
#define DD 1024
#define HH 16
#define DKK 64

// Scratch (allocation-free rule: __device__ globals)
__device__ float g_Q[BB*HH*SS*DKK];      // [b][h][s][dk]
__device__ float g_K[BB*HH*SS*DKK];
__device__ float g_V[BB*HH*SS*DKK];
__device__ float g_attn[BB*SS*DD];       // [b][s][h*64+dk]

// ---------------------------------------------------------------------------
// GEMM: C[m,n] = sum_k A[m,k] * W[n,k] + bias[n]   (torch Linear: x @ W^T + b)
// M=4096, N=1024, K=1024. 128x128x8 tiles, 256 threads, 8x8 per thread
// (split into 2x2 fragments of 4x4 for conflict-free LDS.128).
// HEAD_REORDER: write to [b][h][s][dk] instead of [m][n].
// ---------------------------------------------------------------------------
template<bool HEAD_REORDER>
__global__ void __launch_bounds__(256, 2)
gemm_nt(const float* __restrict__ A, const float* __restrict__ W,
        const float* __restrict__ bias, float* __restrict__ C)
{
    __shared__ float As[8][128];
    __shared__ float Ws[8][128];
    const int bm = blockIdx.y * 128;
    const int bn = blockIdx.x * 128;
    const int tid = threadIdx.x;
    const int tx = tid & 15;
    const int ty = tid >> 4;

    float acc[8][8];
#pragma unroll
    for (int i = 0; i < 8; i++)
#pragma unroll
        for (int j = 0; j < 8; j++) acc[i][j] = 0.f;

    const int lrow = tid >> 1;          // 0..127
    const int lseg = (tid & 1) * 4;     // 0 or 4
    const float* Ap = A + (size_t)(bm + lrow) * 1024 + lseg;
    const float* Wp = W + (size_t)(bn + lrow) * 1024 + lseg;

    for (int k0 = 0; k0 < 1024; k0 += 8) {
        float4 av = *(const float4*)(Ap + k0);
        float4 wv = *(const float4*)(Wp + k0);
        __syncthreads();
        As[lseg+0][lrow] = av.x; As[lseg+1][lrow] = av.y;
        As[lseg+2][lrow] = av.z; As[lseg+3][lrow] = av.w;
        Ws[lseg+0][lrow] = wv.x; Ws[lseg+1][lrow] = wv.y;
        Ws[lseg+2][lrow] = wv.z; Ws[lseg+3][lrow] = wv.w;
        __syncthreads();
#pragma unroll
        for (int k = 0; k < 8; k++) {
            float4 a0 = *(const float4*)&As[k][ty*4];
            float4 a1 = *(const float4*)&As[k][64 + ty*4];
            float4 w0 = *(const float4*)&Ws[k][tx*4];
            float4 w1 = *(const float4*)&Ws[k][64 + tx*4];
            float ar[8] = {a0.x,a0.y,a0.z,a0.w,a1.x,a1.y,a1.z,a1.w};
            float wr[8] = {w0.x,w0.y,w0.z,w0.w,w1.x,w1.y,w1.z,w1.w};
#pragma unroll
            for (int i = 0; i < 8; i++)
#pragma unroll
                for (int j = 0; j < 8; j++)
                    acc[i][j] += ar[i] * wr[j];
        }
    }

#pragma unroll
    for (int rh = 0; rh < 2; rh++) {
#pragma unroll
        for (int i = 0; i < 4; i++) {
            int m = bm + rh*64 + ty*4 + i;
            int b = m >> 11;            // / 2048
            int s = m & 2047;
#pragma unroll
            for (int ch = 0; ch < 2; ch++) {
                int n0 = bn + ch*64 + tx*4;
                float4 v;
                v.x = acc[rh*4+i][ch*4+0] + bias[n0+0];
                v.y = acc[rh*4+i][ch*4+1] + bias[n0+1];
                v.z = acc[rh*4+i][ch*4+2] + bias[n0+2];
                v.w = acc[rh*4+i][ch*4+3] + bias[n0+3];
                size_t idx;
                if (HEAD_REORDER) {
                    int h  = n0 >> 6;
                    int dk = n0 & 63;
                    idx = ((size_t)(b*HH + h) * SS + s) * DKK + dk;
                } else {
                    idx = (size_t)m * DD + n0;
                }
                *(float4*)(C + idx) = v;
            }
        }
    }
}

// ---------------------------------------------------------------------------
// Flash attention (fp32, causal). One block = 64 queries of one (b,h).
// 256 threads as 16x16; each thread owns a 4x4 of the 64x64 score tile and
// a 4(row)x4(dk) slice of the output. Online softmax state replicated across
// the 16 lanes of each row group via shfl_xor(width 16).
// ---------------------------------------------------------------------------
#define AST 68   // smem row stride (floats): pad keeps float4 alignment + banks

__global__ void __launch_bounds__(256)
attn_kernel()
{
    extern __shared__ float sm[];
    float* Qs = sm;               // [64][AST]  natural  [r][dk]
    float* Kt = sm + 64*AST;      // [64][AST]  transposed [dk][c]
    float* Vs = sm + 2*64*AST;    // [64][AST]  natural  [c][dk]
    float* Ps = sm + 3*64*AST;    // [64][AST]  natural  [r][c]

    const int qt = blockIdx.x;    // query tile 0..31
    const int bh = blockIdx.y;    // b*H + h, 0..31
    const int tid = threadIdx.x;
    const int tx = tid & 15;
    const int ty = tid >> 4;

    const float* Qg = g_Q + (size_t)bh * SS * DKK + (size_t)qt * 64 * DKK;
    const float* Kg = g_K + (size_t)bh * SS * DKK;
    const float* Vg = g_V + (size_t)bh * SS * DKK;

    // Load Q tile (natural layout, coalesced)
    for (int i = tid; i < 64*16; i += 256) {
        int r = i >> 4, seg = (i & 15) * 4;
        *(float4*)&Qs[r*AST + seg] = *(const float4*)(Qg + r*64 + seg);
    }

    float m_i[4], l_i[4], acc[4][4];
#pragma unroll
    for (int i = 0; i < 4; i++) {
        m_i[i] = -INFINITY; l_i[i] = 0.f;
#pragma unroll
        for (int j = 0; j < 4; j++) acc[i][j] = 0.f;
    }

    const float scale = 0.125f;   // 1/sqrt(64)

    for (int kt = 0; kt <= qt; kt++) {
        __syncthreads();   // previous tile's Ps/Vs reads complete
        // Load K (transposed into [dk][c]) and V (natural)
        for (int i = tid; i < 64*16; i += 256) {
            int r = i >> 4, seg = (i & 15) * 4;
            float4 kv = *(const float4*)(Kg + (size_t)(kt*64 + r)*64 + seg);
            Kt[(seg+0)*AST + r] = kv.x;
            Kt[(seg+1)*AST + r] = kv.y;
            Kt[(seg+2)*AST + r] = kv.z;
            Kt[(seg+3)*AST + r] = kv.w;
            *(float4*)&Vs[r*AST + seg] =
                *(const float4*)(Vg + (size_t)(kt*64 + r)*64 + seg);
        }
        __syncthreads();

        // S = Q K^T
        float s[4][4];
#pragma unroll
        for (int i = 0; i < 4; i++)
#pragma unroll
            for (int j = 0; j < 4; j++) s[i][j] = 0.f;

#pragma unroll 8
        for (int dk = 0; dk < 64; dk++) {
            float4 kk = *(const float4*)&Kt[dk*AST + tx*4];
#pragma unroll
            for (int i = 0; i < 4; i++) {
                float q = Qs[(ty*4+i)*AST + dk];
                s[i][0] += q*kk.x; s[i][1] += q*kk.y;
                s[i][2] += q*kk.z; s[i][3] += q*kk.w;
            }
        }

        const bool diag = (kt == qt);
#pragma unroll
        for (int i = 0; i < 4; i++) {
            int qi = ty*4 + i;
#pragma unroll
            for (int j = 0; j < 4; j++) {
                s[i][j] *= scale;
                if (diag && (tx*4 + j > qi)) s[i][j] = -INFINITY;
            }
        }

        // Online softmax per row (row group = 16 lanes sharing ty)
#pragma unroll
        for (int i = 0; i < 4; i++) {
            float mx = fmaxf(fmaxf(s[i][0], s[i][1]), fmaxf(s[i][2], s[i][3]));
#pragma unroll
            for (int off = 8; off >= 1; off >>= 1)
                mx = fmaxf(mx, __shfl_xor_sync(0xffffffffu, mx, off));
            float m_new = fmaxf(m_i[i], mx);
            float corr  = __expf(m_i[i] - m_new);   // 0 on first tile (m_i=-inf)
            float p0 = __expf(s[i][0] - m_new);
            float p1 = __expf(s[i][1] - m_new);
            float p2 = __expf(s[i][2] - m_new);
            float p3 = __expf(s[i][3] - m_new);
            float rs = (p0 + p1) + (p2 + p3);
#pragma unroll
            for (int off = 8; off >= 1; off >>= 1)
                rs += __shfl_xor_sync(0xffffffffu, rs, off);
            l_i[i] = l_i[i]*corr + rs;
            m_i[i] = m_new;
#pragma unroll
            for (int j = 0; j < 4; j++) acc[i][j] *= corr;
            *(float4*)&Ps[(ty*4+i)*AST + tx*4] = make_float4(p0, p1, p2, p3);
        }
        __syncthreads();

        // O += P @ V
#pragma unroll 8
        for (int k = 0; k < 64; k++) {
            float4 vv = *(const float4*)&Vs[k*AST + tx*4];
#pragma unroll
            for (int i = 0; i < 4; i++) {
                float pp = Ps[(ty*4+i)*AST + k];
                acc[i][0] += pp*vv.x; acc[i][1] += pp*vv.y;
                acc[i][2] += pp*vv.z; acc[i][3] += pp*vv.w;
            }
        }
    }

    // Epilogue: g_attn[b][s][h*64+dk]
    const int b = bh >> 4;
    const int h = bh & 15;
#pragma unroll
    for (int i = 0; i < 4; i++) {
        float inv = 1.f / l_i[i];
        int srow = qt*64 + ty*4 + i;
        float4 v = make_float4(acc[i][0]*inv, acc[i][1]*inv,
                               acc[i][2]*inv, acc[i][3]*inv);
        size_t idx = ((size_t)(b*SS + srow)) * DD + h*64 + tx*4;
        *(float4*)(g_attn + idx) = v;
    }
}

// ---------------------------------------------------------------------------
extern "C" void kernel_launch(void* const* d_in, const int* in_sizes, int n_in,
                              void* d_out, int out_size)
{
    const float* query = (const float*)d_in[0];
    const float* key_  = (const float*)d_in[1];
    const float* value = (const float*)d_in[2];
    // d_in[3] = mask: always causal (tril) for this problem -> handled structurally
    const float* W_q = (const float*)d_in[4];
    const float* b_q = (const float*)d_in[5];
    const float* W_k = (const float*)d_in[6];
    const float* b_k = (const float*)d_in[7];
    const float* W_v = (const float*)d_in[8];
    const float* b_v = (const float*)d_in[9];
    const float* W_o = (const float*)d_in[10];
    const float* b_o = (const float*)d_in[11];

    float *Qp, *Kp, *Vp, *Ap;
    cudaGetSymbolAddress((void**)&Qp, g_Q);
    cudaGetSymbolAddress((void**)&Kp, g_K);
    cudaGetSymbolAddress((void**)&Vp, g_V);
    cudaGetSymbolAddress((void**)&Ap, g_attn);

    dim3 ggrid(DD/128, (BB*SS)/128);   // (8, 32)
    gemm_nt<true><<<ggrid, 256>>>(query, W_q, b_q, Qp);
    gemm_nt<true><<<ggrid, 256>>>(key_,  W_k, b_k, Kp);
    gemm_nt<true><<<ggrid, 256>>>(value, W_v, b_v, Vp);

    int smem = 4 * 64 * AST * (int)sizeof(float);   // 69632 B
    cudaFuncSetAttribute(attn_kernel,
                         cudaFuncAttributeMaxDynamicSharedMemorySize, smem);
    attn_kernel<<<dim3(SS/64, BB*HH), 256, smem>>>();

    gemm_nt<false><<<ggrid, 256>>>(Ap, W_o, b_o, (float*)d_out);
}

// round 3
// speedup vs baseline: 1.4807x; 1.4807x over previous
#include <cuda_runtime.h>
#include <math.h>
#include <stdint.h>

#define BB 2
#define SS 2048
#define DD 1024
#define HH 16
#define DKK 64

// Scratch (allocation-free rule: __device__ globals)
__device__ float g_Q[BB*HH*SS*DKK];      // [b][h][s][dk]
__device__ float g_K[BB*HH*SS*DKK];
__device__ float g_V[BB*HH*SS*DKK];
__device__ float g_attn[BB*SS*DD];       // [b][s][h*64+dk]

__device__ __forceinline__ float tf32r(float x) {
    float r; asm("cvt.rna.tf32.f32 %0, %1;" : "=f"(r) : "f"(x)); return r;
}

__device__ __forceinline__ void mma_tf32(float& d0, float& d1, float& d2, float& d3,
                                         uint32_t a0, uint32_t a1, uint32_t a2, uint32_t a3,
                                         uint32_t b0, uint32_t b1)
{
    asm volatile(
        "mma.sync.aligned.m16n8k8.row.col.f32.tf32.tf32.f32 "
        "{%0,%1,%2,%3}, {%4,%5,%6,%7}, {%8,%9}, {%0,%1,%2,%3};"
        : "+f"(d0), "+f"(d1), "+f"(d2), "+f"(d3)
        : "r"(a0), "r"(a1), "r"(a2), "r"(a3), "r"(b0), "r"(b1));
}

// ===========================================================================
// tf32 mma.sync GEMM: C[m,n] = sum_k A[m,k]*W[n,k] + bias[n]
// M=4096, N=1024, K=1024. CTA: 128x128 tile. 8 warps (2 rows x 4 cols), each
// warp 64x32 via 4x4 grid of m16n8k8. K chunked by 16, register-staged
// (load chunk i+1 from gmem while computing chunk i from smem).
// SMEM row stride 20 floats => fragment LDS is 32-bank conflict-free.
// ===========================================================================
#define KC 16
#define LDS_STRIDE 20

template<bool REORDER>
__global__ void __launch_bounds__(256, 2)
gemm_mma(const float* __restrict__ A, const float* __restrict__ W,
         const float* __restrict__ bias, float* __restrict__ C)
{
    __shared__ float As[128 * LDS_STRIDE];
    __shared__ float Ws[128 * LDS_STRIDE];

    const int tid = threadIdx.x;
    const int bm = blockIdx.y * 128;
    const int bn = blockIdx.x * 128;

    const int wid  = tid >> 5;
    const int lane = tid & 31;
    const int warpM = wid >> 2;        // 0..1 (64 rows each)
    const int warpN = wid & 3;         // 0..3 (32 cols each)
    const int g = lane >> 2;           // 0..7
    const int t = lane & 3;            // 0..3

    // staging addresses: thread covers rows (tid>>2) and (tid>>2)+64,
    // cols (tid&3)*4 .. +3  (of the 16-wide chunk)
    const int srow = tid >> 2;
    const int scol = (tid & 3) * 4;
    const float* Ag = A + (size_t)(bm + srow) * 1024 + scol;
    const float* Wg = W + (size_t)(bn + srow) * 1024 + scol;

    float acc[16][4];
#pragma unroll
    for (int i = 0; i < 16; i++)
#pragma unroll
        for (int j = 0; j < 4; j++) acc[i][j] = 0.f;

    // prologue: load chunk 0
    float4 rA0 = *(const float4*)(Ag);
    float4 rA1 = *(const float4*)(Ag + 64 * 1024);
    float4 rB0 = *(const float4*)(Wg);
    float4 rB1 = *(const float4*)(Wg + 64 * 1024);

    for (int c = 0; c < 64; c++) {
        // store staged regs (tf32-rounded) to smem
        {
            float4 v;
            v = rA0; v.x=tf32r(v.x); v.y=tf32r(v.y); v.z=tf32r(v.z); v.w=tf32r(v.w);
            *(float4*)&As[srow * LDS_STRIDE + scol] = v;
            v = rA1; v.x=tf32r(v.x); v.y=tf32r(v.y); v.z=tf32r(v.z); v.w=tf32r(v.w);
            *(float4*)&As[(srow + 64) * LDS_STRIDE + scol] = v;
            v = rB0; v.x=tf32r(v.x); v.y=tf32r(v.y); v.z=tf32r(v.z); v.w=tf32r(v.w);
            *(float4*)&Ws[srow * LDS_STRIDE + scol] = v;
            v = rB1; v.x=tf32r(v.x); v.y=tf32r(v.y); v.z=tf32r(v.z); v.w=tf32r(v.w);
            *(float4*)&Ws[(srow + 64) * LDS_STRIDE + scol] = v;
        }
        __syncthreads();

        // issue loads for next chunk (overlap with compute below)
        if (c < 63) {
            const float* An = Ag + (c + 1) * KC;
            const float* Wn = Wg + (c + 1) * KC;
            rA0 = *(const float4*)(An);
            rA1 = *(const float4*)(An + 64 * 1024);
            rB0 = *(const float4*)(Wn);
            rB1 = *(const float4*)(Wn + 64 * 1024);
        }

        // compute: 2 ksteps of 8
#pragma unroll
        for (int ks = 0; ks < 2; ks++) {
            const int k0 = ks * 8;
            uint32_t af[4][4], bf[4][2];
#pragma unroll
            for (int mt = 0; mt < 4; mt++) {
                const float* ap = &As[(warpM * 64 + mt * 16 + g) * LDS_STRIDE + k0 + t];
                af[mt][0] = __float_as_uint(ap[0]);
                af[mt][1] = __float_as_uint(ap[8 * LDS_STRIDE]);
                af[mt][2] = __float_as_uint(ap[4]);
                af[mt][3] = __float_as_uint(ap[8 * LDS_STRIDE + 4]);
            }
#pragma unroll
            for (int nt = 0; nt < 4; nt++) {
                const float* bp = &Ws[(warpN * 32 + nt * 8 + g) * LDS_STRIDE + k0 + t];
                bf[nt][0] = __float_as_uint(bp[0]);
                bf[nt][1] = __float_as_uint(bp[4]);
            }
#pragma unroll
            for (int mt = 0; mt < 4; mt++)
#pragma unroll
                for (int nt = 0; nt < 4; nt++)
                    mma_tf32(acc[mt*4+nt][0], acc[mt*4+nt][1],
                             acc[mt*4+nt][2], acc[mt*4+nt][3],
                             af[mt][0], af[mt][1], af[mt][2], af[mt][3],
                             bf[nt][0], bf[nt][1]);
        }
        __syncthreads();
    }

    // Epilogue: c0,c1 at (row g, cols 2t,2t+1), c2,c3 at (row g+8)
#pragma unroll
    for (int mt = 0; mt < 4; mt++) {
#pragma unroll
        for (int nt = 0; nt < 4; nt++) {
            const int n0 = bn + warpN * 32 + nt * 8 + 2 * t;
            const float2 bb = *(const float2*)(bias + n0);
#pragma unroll
            for (int half = 0; half < 2; half++) {
                const int m = bm + warpM * 64 + mt * 16 + g + half * 8;
                float2 v;
                v.x = acc[mt*4+nt][half*2+0] + bb.x;
                v.y = acc[mt*4+nt][half*2+1] + bb.y;
                size_t idx;
                if (REORDER) {
                    const int b = m >> 11, s = m & 2047;
                    const int h = n0 >> 6, dk = n0 & 63;
                    idx = ((size_t)(b * HH + h) * SS + s) * DKK + dk;
                } else {
                    idx = (size_t)m * DD + n0;
                }
                *(float2*)(C + idx) = v;
            }
        }
    }
}

// ---------------------------------------------------------------------------
// Flash attention (fp32, causal). One block = 64 queries of one (b,h).
// (unchanged from R1 — target for Round 3)
// ---------------------------------------------------------------------------
#define AST 68

__global__ void __launch_bounds__(256)
attn_kernel()
{
    extern __shared__ float smf[];
    float* Qs = smf;
    float* Kt = smf + 64*AST;
    float* Vs = smf + 2*64*AST;
    float* Ps = smf + 3*64*AST;

    const int qt = blockIdx.x;
    const int bh = blockIdx.y;
    const int tid = threadIdx.x;
    const int tx = tid & 15;
    const int ty = tid >> 4;

    const float* Qg = g_Q + (size_t)bh * SS * DKK + (size_t)qt * 64 * DKK;
    const float* Kg = g_K + (size_t)bh * SS * DKK;
    const float* Vg = g_V + (size_t)bh * SS * DKK;

    for (int i = tid; i < 64*16; i += 256) {
        int r = i >> 4, seg = (i & 15) * 4;
        *(float4*)&Qs[r*AST + seg] = *(const float4*)(Qg + r*64 + seg);
    }

    float m_i[4], l_i[4], acc[4][4];
#pragma unroll
    for (int i = 0; i < 4; i++) {
        m_i[i] = -INFINITY; l_i[i] = 0.f;
#pragma unroll
        for (int j = 0; j < 4; j++) acc[i][j] = 0.f;
    }

    const float scale = 0.125f;

    for (int kt = 0; kt <= qt; kt++) {
        __syncthreads();
        for (int i = tid; i < 64*16; i += 256) {
            int r = i >> 4, seg = (i & 15) * 4;
            float4 kv = *(const float4*)(Kg + (size_t)(kt*64 + r)*64 + seg);
            Kt[(seg+0)*AST + r] = kv.x;
            Kt[(seg+1)*AST + r] = kv.y;
            Kt[(seg+2)*AST + r] = kv.z;
            Kt[(seg+3)*AST + r] = kv.w;
            *(float4*)&Vs[r*AST + seg] =
                *(const float4*)(Vg + (size_t)(kt*64 + r)*64 + seg);
        }
        __syncthreads();

        float s[4][4];
#pragma unroll
        for (int i = 0; i < 4; i++)
#pragma unroll
            for (int j = 0; j < 4; j++) s[i][j] = 0.f;

#pragma unroll 8
        for (int dk = 0; dk < 64; dk++) {
            float4 kk = *(const float4*)&Kt[dk*AST + tx*4];
#pragma unroll
            for (int i = 0; i < 4; i++) {
                float q = Qs[(ty*4+i)*AST + dk];
                s[i][0] += q*kk.x; s[i][1] += q*kk.y;
                s[i][2] += q*kk.z; s[i][3] += q*kk.w;
            }
        }

        const bool diag = (kt == qt);
#pragma unroll
        for (int i = 0; i < 4; i++) {
            int qi = ty*4 + i;
#pragma unroll
            for (int j = 0; j < 4; j++) {
                s[i][j] *= scale;
                if (diag && (tx*4 + j > qi)) s[i][j] = -INFINITY;
            }
        }

#pragma unroll
        for (int i = 0; i < 4; i++) {
            float mx = fmaxf(fmaxf(s[i][0], s[i][1]), fmaxf(s[i][2], s[i][3]));
#pragma unroll
            for (int off = 8; off >= 1; off >>= 1)
                mx = fmaxf(mx, __shfl_xor_sync(0xffffffffu, mx, off));
            float m_new = fmaxf(m_i[i], mx);
            float corr  = __expf(m_i[i] - m_new);
            float p0 = __expf(s[i][0] - m_new);
            float p1 = __expf(s[i][1] - m_new);
            float p2 = __expf(s[i][2] - m_new);
            float p3 = __expf(s[i][3] - m_new);
            float rs = (p0 + p1) + (p2 + p3);
#pragma unroll
            for (int off = 8; off >= 1; off >>= 1)
                rs += __shfl_xor_sync(0xffffffffu, rs, off);
            l_i[i] = l_i[i]*corr + rs;
            m_i[i] = m_new;
#pragma unroll
            for (int j = 0; j < 4; j++) acc[i][j] *= corr;
            *(float4*)&Ps[(ty*4+i)*AST + tx*4] = make_float4(p0, p1, p2, p3);
        }
        __syncthreads();

#pragma unroll 8
        for (int k = 0; k < 64; k++) {
            float4 vv = *(const float4*)&Vs[k*AST + tx*4];
#pragma unroll
            for (int i = 0; i < 4; i++) {
                float pp = Ps[(ty*4+i)*AST + k];
                acc[i][0] += pp*vv.x; acc[i][1] += pp*vv.y;
                acc[i][2] += pp*vv.z; acc[i][3] += pp*vv.w;
            }
        }
    }

    const int b = bh >> 4;
    const int h = bh & 15;
#pragma unroll
    for (int i = 0; i < 4; i++) {
        float inv = 1.f / l_i[i];
        int srow = qt*64 + ty*4 + i;
        float4 v = make_float4(acc[i][0]*inv, acc[i][1]*inv,
                               acc[i][2]*inv, acc[i][3]*inv);
        size_t idx = ((size_t)(b*SS + srow)) * DD + h*64 + tx*4;
        *(float4*)(g_attn + idx) = v;
    }
}

// ---------------------------------------------------------------------------
extern "C" void kernel_launch(void* const* d_in, const int* in_sizes, int n_in,
                              void* d_out, int out_size)
{
    const float* query = (const float*)d_in[0];
    const float* key_  = (const float*)d_in[1];
    const float* value = (const float*)d_in[2];
    // d_in[3] = mask: causal (tril) -> handled structurally
    const float* W_q = (const float*)d_in[4];
    const float* b_q = (const float*)d_in[5];
    const float* W_k = (const float*)d_in[6];
    const float* b_k = (const float*)d_in[7];
    const float* W_v = (const float*)d_in[8];
    const float* b_v = (const float*)d_in[9];
    const float* W_o = (const float*)d_in[10];
    const float* b_o = (const float*)d_in[11];

    float *Qp, *Kp, *Vp, *Ap;
    cudaGetSymbolAddress((void**)&Qp, g_Q);
    cudaGetSymbolAddress((void**)&Kp, g_K);
    cudaGetSymbolAddress((void**)&Vp, g_V);
    cudaGetSymbolAddress((void**)&Ap, g_attn);

    dim3 ggrid(DD/128, (BB*SS)/128);   // (8, 32)
    gemm_mma<true><<<ggrid, 256>>>(query, W_q, b_q, Qp);
    gemm_mma<true><<<ggrid, 256>>>(key_,  W_k, b_k, Kp);
    gemm_mma<true><<<ggrid, 256>>>(value, W_v, b_v, Vp);

    int smem = 4 * 64 * AST * (int)sizeof(float);   // 69632 B
    cudaFuncSetAttribute(attn_kernel,
                         cudaFuncAttributeMaxDynamicSharedMemorySize, smem);
    attn_kernel<<<dim3(SS/64, BB*HH), 256, smem>>>();

    gemm_mma<false><<<ggrid, 256>>>(Ap, W_o, b_o, (float*)d_out);
}

// round 4
// speedup vs baseline: 2.2842x; 1.5427x over previous
#include <cuda_runtime.h>
#include <math.h>
#include <stdint.h>

#define BB 2
#define SS 2048
#define DD 1024
#define HH 16
#define DKK 64

// Scratch (allocation-free rule: __device__ globals)
__device__ float g_Q[BB*HH*SS*DKK];      // [b][h][s][dk]
__device__ float g_K[BB*HH*SS*DKK];
__device__ float g_V[BB*HH*SS*DKK];
__device__ float g_attn[BB*SS*DD];       // [b][s][h*64+dk]

__device__ __forceinline__ float tf32r(float x) {
    float r; asm("cvt.rna.tf32.f32 %0, %1;" : "=f"(r) : "f"(x)); return r;
}

__device__ __forceinline__ void mma_tf32(float& d0, float& d1, float& d2, float& d3,
                                         uint32_t a0, uint32_t a1, uint32_t a2, uint32_t a3,
                                         uint32_t b0, uint32_t b1)
{
    asm volatile(
        "mma.sync.aligned.m16n8k8.row.col.f32.tf32.tf32.f32 "
        "{%0,%1,%2,%3}, {%4,%5,%6,%7}, {%8,%9}, {%0,%1,%2,%3};"
        : "+f"(d0), "+f"(d1), "+f"(d2), "+f"(d3)
        : "r"(a0), "r"(a1), "r"(a2), "r"(a3), "r"(b0), "r"(b1));
}

// ===========================================================================
// tf32 mma.sync GEMM (unchanged from R3): C = A @ W^T + bias
// ===========================================================================
#define KC 16
#define LDS_STRIDE 20

template<bool REORDER>
__global__ void __launch_bounds__(256, 2)
gemm_mma(const float* __restrict__ A, const float* __restrict__ W,
         const float* __restrict__ bias, float* __restrict__ C)
{
    __shared__ float As[128 * LDS_STRIDE];
    __shared__ float Ws[128 * LDS_STRIDE];

    const int tid = threadIdx.x;
    const int bm = blockIdx.y * 128;
    const int bn = blockIdx.x * 128;

    const int wid  = tid >> 5;
    const int lane = tid & 31;
    const int warpM = wid >> 2;
    const int warpN = wid & 3;
    const int g = lane >> 2;
    const int t = lane & 3;

    const int srow = tid >> 2;
    const int scol = (tid & 3) * 4;
    const float* Ag = A + (size_t)(bm + srow) * 1024 + scol;
    const float* Wg = W + (size_t)(bn + srow) * 1024 + scol;

    float acc[16][4];
#pragma unroll
    for (int i = 0; i < 16; i++)
#pragma unroll
        for (int j = 0; j < 4; j++) acc[i][j] = 0.f;

    float4 rA0 = *(const float4*)(Ag);
    float4 rA1 = *(const float4*)(Ag + 64 * 1024);
    float4 rB0 = *(const float4*)(Wg);
    float4 rB1 = *(const float4*)(Wg + 64 * 1024);

    for (int c = 0; c < 64; c++) {
        {
            float4 v;
            v = rA0; v.x=tf32r(v.x); v.y=tf32r(v.y); v.z=tf32r(v.z); v.w=tf32r(v.w);
            *(float4*)&As[srow * LDS_STRIDE + scol] = v;
            v = rA1; v.x=tf32r(v.x); v.y=tf32r(v.y); v.z=tf32r(v.z); v.w=tf32r(v.w);
            *(float4*)&As[(srow + 64) * LDS_STRIDE + scol] = v;
            v = rB0; v.x=tf32r(v.x); v.y=tf32r(v.y); v.z=tf32r(v.z); v.w=tf32r(v.w);
            *(float4*)&Ws[srow * LDS_STRIDE + scol] = v;
            v = rB1; v.x=tf32r(v.x); v.y=tf32r(v.y); v.z=tf32r(v.z); v.w=tf32r(v.w);
            *(float4*)&Ws[(srow + 64) * LDS_STRIDE + scol] = v;
        }
        __syncthreads();

        if (c < 63) {
            const float* An = Ag + (c + 1) * KC;
            const float* Wn = Wg + (c + 1) * KC;
            rA0 = *(const float4*)(An);
            rA1 = *(const float4*)(An + 64 * 1024);
            rB0 = *(const float4*)(Wn);
            rB1 = *(const float4*)(Wn + 64 * 1024);
        }

#pragma unroll
        for (int ks = 0; ks < 2; ks++) {
            const int k0 = ks * 8;
            uint32_t af[4][4], bf[4][2];
#pragma unroll
            for (int mt = 0; mt < 4; mt++) {
                const float* ap = &As[(warpM * 64 + mt * 16 + g) * LDS_STRIDE + k0 + t];
                af[mt][0] = __float_as_uint(ap[0]);
                af[mt][1] = __float_as_uint(ap[8 * LDS_STRIDE]);
                af[mt][2] = __float_as_uint(ap[4]);
                af[mt][3] = __float_as_uint(ap[8 * LDS_STRIDE + 4]);
            }
#pragma unroll
            for (int nt = 0; nt < 4; nt++) {
                const float* bp = &Ws[(warpN * 32 + nt * 8 + g) * LDS_STRIDE + k0 + t];
                bf[nt][0] = __float_as_uint(bp[0]);
                bf[nt][1] = __float_as_uint(bp[4]);
            }
#pragma unroll
            for (int mt = 0; mt < 4; mt++)
#pragma unroll
                for (int nt = 0; nt < 4; nt++)
                    mma_tf32(acc[mt*4+nt][0], acc[mt*4+nt][1],
                             acc[mt*4+nt][2], acc[mt*4+nt][3],
                             af[mt][0], af[mt][1], af[mt][2], af[mt][3],
                             bf[nt][0], bf[nt][1]);
        }
        __syncthreads();
    }

#pragma unroll
    for (int mt = 0; mt < 4; mt++) {
#pragma unroll
        for (int nt = 0; nt < 4; nt++) {
            const int n0 = bn + warpN * 32 + nt * 8 + 2 * t;
            const float2 bb = *(const float2*)(bias + n0);
#pragma unroll
            for (int half = 0; half < 2; half++) {
                const int m = bm + warpM * 64 + mt * 16 + g + half * 8;
                float2 v;
                v.x = acc[mt*4+nt][half*2+0] + bb.x;
                v.y = acc[mt*4+nt][half*2+1] + bb.y;
                size_t idx;
                if (REORDER) {
                    const int b = m >> 11, s = m & 2047;
                    const int h = n0 >> 6, dk = n0 & 63;
                    idx = ((size_t)(b * HH + h) * SS + s) * DKK + dk;
                } else {
                    idx = (size_t)m * DD + n0;
                }
                *(float2*)(C + idx) = v;
            }
        }
    }
}

// ===========================================================================
// Flash attention on tensor cores (tf32 mma.sync, causal).
// CTA: 128 queries x one (b,h); 8 warps, each one m16 row band.
// Key tiles of 64. S = Q K^T via m16n8k8 (B-frag = K rows, natural layout).
// Softmax on accumulator fragments (quad shfl). P -> smem (tf32) -> A-frags.
// PV via m16n8k8 with B-frag = V^T rows (V transposed at staging,
// conflict-free STS by sweeping the key index across lanes).
// ===========================================================================
#define ATT_ST 68   // ≡ 4 (mod 32): fragment LDS conflict-free
#define ATT_SMEM ((128 + 64 + 64 + 128) * ATT_ST * 4)   // 104448 B

__global__ void __launch_bounds__(256, 2)
attn_mma()
{
    extern __shared__ float smf[];
    float* Qs = smf;                       // [128][ST]  q rows (tf32)
    float* Ks = Qs + 128 * ATT_ST;         // [64][ST]   key rows (tf32)
    float* Vt = Ks + 64 * ATT_ST;          // [64][ST]   Vt[dk][key] (tf32)
    float* Ps = Vt + 64 * ATT_ST;          // [128][ST]  P rows (tf32)

    const int qt  = blockIdx.x;            // 0..15
    const int bh  = blockIdx.y;            // 0..31
    const int tid = threadIdx.x;
    const int wid = tid >> 5;
    const int lane = tid & 31;
    const int g = lane >> 2;                // 0..7
    const int t = lane & 3;                 // 0..3

    const float* Qg = g_Q + (size_t)bh * SS * DKK + (size_t)qt * 128 * DKK;
    const float* Kg = g_K + (size_t)bh * SS * DKK;
    const float* Vg = g_V + (size_t)bh * SS * DKK;

    // Stage Q once (tf32-rounded)
    for (int i = tid; i < 128 * 16; i += 256) {
        int r = i >> 4, seg = (i & 15) * 4;
        float4 v = *(const float4*)(Qg + r * 64 + seg);
        v.x = tf32r(v.x); v.y = tf32r(v.y); v.z = tf32r(v.z); v.w = tf32r(v.w);
        *(float4*)&Qs[r * ATT_ST + seg] = v;
    }

    float o[8][4];
#pragma unroll
    for (int i = 0; i < 8; i++)
#pragma unroll
        for (int j = 0; j < 4; j++) o[i][j] = 0.f;
    float m0 = -INFINITY, m1 = -INFINITY, l0 = 0.f, l1 = 0.f;

    const int row0 = wid * 16;
    const int qrow0 = qt * 128 + row0 + g;      // row of c0,c1 (c2,c3 = +8)
    const int nkt = 2 * qt + 2;

    for (int kt = 0; kt < nkt; kt++) {
        __syncthreads();    // all warps done with previous K/V/P
        // Stage K tile (natural [key][dk])
        for (int i = tid; i < 64 * 16; i += 256) {
            int r = i >> 4, seg = (i & 15) * 4;
            float4 v = *(const float4*)(Kg + (size_t)(kt * 64 + r) * 64 + seg);
            v.x = tf32r(v.x); v.y = tf32r(v.y); v.z = tf32r(v.z); v.w = tf32r(v.w);
            *(float4*)&Ks[r * ATT_ST + seg] = v;
        }
        // Stage V transposed: Vt[dk][key]. Lanes sweep key (r) -> STS banks
        // 4*dk + key all distinct; gmem strided reads are L1-served (16KB tile).
        for (int i = tid; i < 1024; i += 256) {
            int r = i & 63, seg = (i >> 6) * 4;
            float4 v = *(const float4*)(Vg + (size_t)(kt * 64 + r) * 64 + seg);
            Vt[(seg + 0) * ATT_ST + r] = tf32r(v.x);
            Vt[(seg + 1) * ATT_ST + r] = tf32r(v.y);
            Vt[(seg + 2) * ATT_ST + r] = tf32r(v.z);
            Vt[(seg + 3) * ATT_ST + r] = tf32r(v.w);
        }
        __syncthreads();

        // S = Q K^T  (warp's 16 rows x 64 keys)
        float sa[8][4];
#pragma unroll
        for (int i = 0; i < 8; i++)
#pragma unroll
            for (int j = 0; j < 4; j++) sa[i][j] = 0.f;

#pragma unroll
        for (int ks = 0; ks < 8; ks++) {
            const float* ap = &Qs[(row0 + g) * ATT_ST + ks * 8 + t];
            uint32_t a0 = __float_as_uint(ap[0]);
            uint32_t a1 = __float_as_uint(ap[8 * ATT_ST]);
            uint32_t a2 = __float_as_uint(ap[4]);
            uint32_t a3 = __float_as_uint(ap[8 * ATT_ST + 4]);
#pragma unroll
            for (int nt = 0; nt < 8; nt++) {
                const float* bp = &Ks[(nt * 8 + g) * ATT_ST + ks * 8 + t];
                mma_tf32(sa[nt][0], sa[nt][1], sa[nt][2], sa[nt][3],
                         a0, a1, a2, a3,
                         __float_as_uint(bp[0]), __float_as_uint(bp[4]));
            }
        }

        // scale + causal mask (only diagonal-zone tiles need masking)
#pragma unroll
        for (int nt = 0; nt < 8; nt++)
#pragma unroll
            for (int j = 0; j < 4; j++) sa[nt][j] *= 0.125f;

        if (kt >= 2 * qt) {
#pragma unroll
            for (int nt = 0; nt < 8; nt++) {
                int key = kt * 64 + nt * 8 + 2 * t;
                if (key     > qrow0)     sa[nt][0] = -INFINITY;
                if (key + 1 > qrow0)     sa[nt][1] = -INFINITY;
                if (key     > qrow0 + 8) sa[nt][2] = -INFINITY;
                if (key + 1 > qrow0 + 8) sa[nt][3] = -INFINITY;
            }
        }

        // online softmax (rows g and g+8; quad = lanes sharing row)
        float mx0 = -INFINITY, mx1 = -INFINITY;
#pragma unroll
        for (int nt = 0; nt < 8; nt++) {
            mx0 = fmaxf(mx0, fmaxf(sa[nt][0], sa[nt][1]));
            mx1 = fmaxf(mx1, fmaxf(sa[nt][2], sa[nt][3]));
        }
        mx0 = fmaxf(mx0, __shfl_xor_sync(0xffffffffu, mx0, 1));
        mx0 = fmaxf(mx0, __shfl_xor_sync(0xffffffffu, mx0, 2));
        mx1 = fmaxf(mx1, __shfl_xor_sync(0xffffffffu, mx1, 1));
        mx1 = fmaxf(mx1, __shfl_xor_sync(0xffffffffu, mx1, 2));

        float mn0 = fmaxf(m0, mx0), mn1 = fmaxf(m1, mx1);
        float corr0 = __expf(m0 - mn0), corr1 = __expf(m1 - mn1);

        float rs0 = 0.f, rs1 = 0.f;
#pragma unroll
        for (int nt = 0; nt < 8; nt++) {
            sa[nt][0] = __expf(sa[nt][0] - mn0);
            sa[nt][1] = __expf(sa[nt][1] - mn0);
            sa[nt][2] = __expf(sa[nt][2] - mn1);
            sa[nt][3] = __expf(sa[nt][3] - mn1);
            rs0 += sa[nt][0] + sa[nt][1];
            rs1 += sa[nt][2] + sa[nt][3];
        }
        rs0 += __shfl_xor_sync(0xffffffffu, rs0, 1);
        rs0 += __shfl_xor_sync(0xffffffffu, rs0, 2);
        rs1 += __shfl_xor_sync(0xffffffffu, rs1, 1);
        rs1 += __shfl_xor_sync(0xffffffffu, rs1, 2);

        l0 = l0 * corr0 + rs0;  m0 = mn0;
        l1 = l1 * corr1 + rs1;  m1 = mn1;

#pragma unroll
        for (int nt = 0; nt < 8; nt++) {
            o[nt][0] *= corr0; o[nt][1] *= corr0;
            o[nt][2] *= corr1; o[nt][3] *= corr1;
            // write P (tf32-rounded) for PV mma A-fragments
            float2 p01 = make_float2(tf32r(sa[nt][0]), tf32r(sa[nt][1]));
            float2 p23 = make_float2(tf32r(sa[nt][2]), tf32r(sa[nt][3]));
            *(float2*)&Ps[(row0 + g) * ATT_ST + nt * 8 + 2 * t]     = p01;
            *(float2*)&Ps[(row0 + g + 8) * ATT_ST + nt * 8 + 2 * t] = p23;
        }
        __syncthreads();

        // O += P @ V   (A-frags from Ps, B-frags from Vt rows = dk)
#pragma unroll
        for (int ks = 0; ks < 8; ks++) {
            const float* ap = &Ps[(row0 + g) * ATT_ST + ks * 8 + t];
            uint32_t a0 = __float_as_uint(ap[0]);
            uint32_t a1 = __float_as_uint(ap[8 * ATT_ST]);
            uint32_t a2 = __float_as_uint(ap[4]);
            uint32_t a3 = __float_as_uint(ap[8 * ATT_ST + 4]);
#pragma unroll
            for (int nt = 0; nt < 8; nt++) {
                const float* bp = &Vt[(nt * 8 + g) * ATT_ST + ks * 8 + t];
                mma_tf32(o[nt][0], o[nt][1], o[nt][2], o[nt][3],
                         a0, a1, a2, a3,
                         __float_as_uint(bp[0]), __float_as_uint(bp[4]));
            }
        }
    }

    // Epilogue: g_attn[b][s][h*64+dk]
    const int b = bh >> 4;
    const int h = bh & 15;
    const float inv0 = 1.f / l0, inv1 = 1.f / l1;
    const int srow0 = qt * 128 + row0 + g;
#pragma unroll
    for (int nt = 0; nt < 8; nt++) {
        const int dk = nt * 8 + 2 * t;
        size_t i0 = ((size_t)(b * SS + srow0)) * DD + h * 64 + dk;
        size_t i1 = ((size_t)(b * SS + srow0 + 8)) * DD + h * 64 + dk;
        *(float2*)(g_attn + i0) = make_float2(o[nt][0] * inv0, o[nt][1] * inv0);
        *(float2*)(g_attn + i1) = make_float2(o[nt][2] * inv1, o[nt][3] * inv1);
    }
}

// ---------------------------------------------------------------------------
extern "C" void kernel_launch(void* const* d_in, const int* in_sizes, int n_in,
                              void* d_out, int out_size)
{
    const float* query = (const float*)d_in[0];
    const float* key_  = (const float*)d_in[1];
    const float* value = (const float*)d_in[2];
    // d_in[3] = mask: causal (tril) -> handled structurally
    const float* W_q = (const float*)d_in[4];
    const float* b_q = (const float*)d_in[5];
    const float* W_k = (const float*)d_in[6];
    const float* b_k = (const float*)d_in[7];
    const float* W_v = (const float*)d_in[8];
    const float* b_v = (const float*)d_in[9];
    const float* W_o = (const float*)d_in[10];
    const float* b_o = (const float*)d_in[11];

    float *Qp, *Kp, *Vp, *Ap;
    cudaGetSymbolAddress((void**)&Qp, g_Q);
    cudaGetSymbolAddress((void**)&Kp, g_K);
    cudaGetSymbolAddress((void**)&Vp, g_V);
    cudaGetSymbolAddress((void**)&Ap, g_attn);

    dim3 ggrid(DD/128, (BB*SS)/128);   // (8, 32)
    gemm_mma<true><<<ggrid, 256>>>(query, W_q, b_q, Qp);
    gemm_mma<true><<<ggrid, 256>>>(key_,  W_k, b_k, Kp);
    gemm_mma<true><<<ggrid, 256>>>(value, W_v, b_v, Vp);

    cudaFuncSetAttribute(attn_mma,
                         cudaFuncAttributeMaxDynamicSharedMemorySize, ATT_SMEM);
    attn_mma<<<dim3(SS/128, BB*HH), 256, ATT_SMEM>>>();

    gemm_mma<false><<<ggrid, 256>>>(Ap, W_o, b_o, (float*)d_out);
}